// round 7
// baseline (speedup 1.0000x reference)
#include <cuda_runtime.h>

typedef unsigned long long ull;

#define NBATCH 2
#define SEQ 1024
#define DMODEL 768
#define NH 12
#define DH 64
#define NTOK (NBATCH*SEQ)
#define NN (SEQ*SEQ)
#define ATTN_SCALE 0.125f

// ---------------- scratch (device globals: allocation-free) ----------------
__device__ float g_xn[NTOK*DMODEL];
__device__ float g_q[NBATCH*NH*SEQ*DH];
__device__ float g_k[NBATCH*NH*SEQ*DH];
__device__ float g_v[NBATCH*NH*SEQ*DH];
__device__ float g_attn[NBATCH*NH*NN];   // 100.7 MB; softmax+mix in place
__device__ float g_av[NTOK*DMODEL];
__device__ float g_M[NH*NH];

// ---------------- f32x2 packed-FMA helpers (FFMA2, PTX-only path) ----------
__device__ __forceinline__ ull pk2(float x) {
    ull r; asm("mov.b64 %0, {%1, %1};" : "=l"(r) : "f"(x)); return r;
}
__device__ __forceinline__ void fma2(ull& d, ull a, ull b) {
    asm("fma.rn.f32x2 %0, %1, %2, %0;" : "+l"(d) : "l"(a), "l"(b));
}
__device__ __forceinline__ float2 up2(ull v) {
    float2 r; asm("mov.b64 {%0, %1}, %2;" : "=f"(r.x), "=f"(r.y) : "l"(v)); return r;
}

// ---------------- LayerNorm ----------------
__global__ __launch_bounds__(256) void ln_kernel(
    const float* __restrict__ x, const float* __restrict__ g, const float* __restrict__ b)
{
    const int row = blockIdx.x;
    const int t = threadIdx.x;
    const float* xr = x + (size_t)row * DMODEL;
    float v0 = xr[t], v1 = xr[t + 256], v2 = xr[t + 512];
    float s = v0 + v1 + v2;
    float q = v0*v0 + v1*v1 + v2*v2;
    __shared__ float rs[8], rq[8], mb[2];
    #pragma unroll
    for (int o = 16; o; o >>= 1) {
        s += __shfl_xor_sync(0xffffffffu, s, o);
        q += __shfl_xor_sync(0xffffffffu, q, o);
    }
    if ((t & 31) == 0) { rs[t >> 5] = s; rq[t >> 5] = q; }
    __syncthreads();
    if (t == 0) {
        float ts = 0.f, tq = 0.f;
        #pragma unroll
        for (int i = 0; i < 8; i++) { ts += rs[i]; tq += rq[i]; }
        float mean = ts * (1.0f / DMODEL);
        float var  = tq * (1.0f / DMODEL) - mean * mean;
        mb[0] = mean; mb[1] = rsqrtf(var + 1e-5f);
    }
    __syncthreads();
    const float mean = mb[0], rstd = mb[1];
    float* o = g_xn + (size_t)row * DMODEL;
    o[t]       = (v0 - mean) * rstd * g[t]       + b[t];
    o[t + 256] = (v1 - mean) * rstd * g[t + 256] + b[t + 256];
    o[t + 512] = (v2 - mean) * rstd * g[t + 512] + b[t + 512];
}

// ---------------- M = (-0.5 * theta) @ gnn_w  (12x12) ----------------
__global__ void m_kernel(const float* __restrict__ theta, const float* __restrict__ gnn)
{
    int t = threadIdx.x;
    if (t < NH * NH) {
        int i = t / NH, j = t % NH;
        float s = 0.f;
        #pragma unroll
        for (int k = 0; k < NH; k++) s += theta[i * NH + k] * gnn[k * NH + j];
        g_M[t] = -0.5f * s;
    }
}

// ---------------- generic NT GEMM tile: C[64 x 128] += A[64xK] * B[128xK]^T --
template<int KDIM>
__device__ __forceinline__ void gemm_nt(
    const float* __restrict__ A, int lda,
    const float* __restrict__ B, int ldb,
    ull (&acc)[4][4])
{
    __shared__ __align__(16) float As[16][66];
    __shared__ __align__(16) float Bs[16][130];
    const int t = threadIdx.x;
    const int warp = t >> 5, lane = t & 31;
    const int mb = warp * 8;
    const int nb = lane * 4;
    const int lrow = t >> 2;
    const int lq = (t & 3) * 4;
    const float* Aptr = A + (size_t)lrow * lda + lq;
    const float* Bptr0 = B + (size_t)lrow * ldb + lq;
    const float* Bptr1 = B + (size_t)(lrow + 64) * ldb + lq;

    for (int k0 = 0; k0 < KDIM; k0 += 16) {
        float4 av  = *(const float4*)(Aptr  + k0);
        float4 bv0 = *(const float4*)(Bptr0 + k0);
        float4 bv1 = *(const float4*)(Bptr1 + k0);
        __syncthreads();
        As[lq + 0][lrow] = av.x;  As[lq + 1][lrow] = av.y;
        As[lq + 2][lrow] = av.z;  As[lq + 3][lrow] = av.w;
        Bs[lq + 0][lrow] = bv0.x; Bs[lq + 1][lrow] = bv0.y;
        Bs[lq + 2][lrow] = bv0.z; Bs[lq + 3][lrow] = bv0.w;
        Bs[lq + 0][lrow + 64] = bv1.x; Bs[lq + 1][lrow + 64] = bv1.y;
        Bs[lq + 2][lrow + 64] = bv1.z; Bs[lq + 3][lrow + 64] = bv1.w;
        __syncthreads();
        #pragma unroll
        for (int kk = 0; kk < 16; kk++) {
            ull a0 = *(const ull*)&As[kk][mb + 0];
            ull a1 = *(const ull*)&As[kk][mb + 2];
            ull a2 = *(const ull*)&As[kk][mb + 4];
            ull a3 = *(const ull*)&As[kk][mb + 6];
            ull b0 = pk2(Bs[kk][nb + 0]);
            ull b1 = pk2(Bs[kk][nb + 1]);
            ull b2 = pk2(Bs[kk][nb + 2]);
            ull b3 = pk2(Bs[kk][nb + 3]);
            fma2(acc[0][0], a0, b0); fma2(acc[0][1], a0, b1);
            fma2(acc[0][2], a0, b2); fma2(acc[0][3], a0, b3);
            fma2(acc[1][0], a1, b0); fma2(acc[1][1], a1, b1);
            fma2(acc[1][2], a1, b2); fma2(acc[1][3], a1, b3);
            fma2(acc[2][0], a2, b0); fma2(acc[2][1], a2, b1);
            fma2(acc[2][2], a2, b2); fma2(acc[2][3], a2, b3);
            fma2(acc[3][0], a3, b0); fma2(acc[3][1], a3, b1);
            fma2(acc[3][2], a3, b2); fma2(acc[3][3], a3, b3);
        }
    }
}

// ---------------- QKV GEMM: [2048x768] @ w_qkv^T[768x2304], scatter per head --
__global__ __launch_bounds__(256) void qkv_kernel(const float* __restrict__ w)
{
    ull acc[4][4];
    #pragma unroll
    for (int i = 0; i < 4; i++)
        #pragma unroll
        for (int j = 0; j < 4; j++) acc[i][j] = 0ull;

    const float* A = g_xn + (size_t)blockIdx.y * 64 * DMODEL;
    const float* B = w    + (size_t)blockIdx.x * 128 * DMODEL;
    gemm_nt<DMODEL>(A, DMODEL, B, DMODEL, acc);

    const int warp = threadIdx.x >> 5, lane = threadIdx.x & 31;
    const int c0 = blockIdx.x * 128 + lane * 4;   // global output column
    const int sec = c0 / DMODEL;                  // 0=q, 1=k, 2=v (tile never straddles)
    const int rem = c0 - sec * DMODEL;
    const int h = rem >> 6, d = rem & 63;
    float* dst = (sec == 0) ? g_q : (sec == 1) ? g_k : g_v;

    #pragma unroll
    for (int i = 0; i < 4; i++) {
        float2 c0v = up2(acc[i][0]), c1v = up2(acc[i][1]);
        float2 c2v = up2(acc[i][2]), c3v = up2(acc[i][3]);
        int m = blockIdx.y * 64 + warp * 8 + 2 * i;
        int bt = m >> 10, tok = m & 1023;   // tile of 64 rows never straddles batch
        float* p0 = dst + ((size_t)((bt * NH + h) * SEQ + tok)) * DH + d;
        float* p1 = dst + ((size_t)((bt * NH + h) * SEQ + tok + 1)) * DH + d;
        *(float4*)p0 = make_float4(c0v.x, c1v.x, c2v.x, c3v.x);
        *(float4*)p1 = make_float4(c0v.y, c1v.y, c2v.y, c3v.y);
    }
}

// ---------------- S = Q @ K^T * scale  per (b,h) ----------------
__global__ __launch_bounds__(256) void qk_kernel()
{
    const int bh = blockIdx.z;
    ull acc[4][4];
    #pragma unroll
    for (int i = 0; i < 4; i++)
        #pragma unroll
        for (int j = 0; j < 4; j++) acc[i][j] = 0ull;

    const float* A = g_q + (size_t)bh * SEQ * DH + (size_t)blockIdx.y * 64 * DH;
    const float* B = g_k + (size_t)bh * SEQ * DH + (size_t)blockIdx.x * 128 * DH;
    gemm_nt<DH>(A, DH, B, DH, acc);

    const int warp = threadIdx.x >> 5, lane = threadIdx.x & 31;
    float* out = g_attn + (size_t)bh * NN;
    const int n0 = blockIdx.x * 128 + lane * 4;
    #pragma unroll
    for (int i = 0; i < 4; i++) {
        float2 c0v = up2(acc[i][0]), c1v = up2(acc[i][1]);
        float2 c2v = up2(acc[i][2]), c3v = up2(acc[i][3]);
        int m = blockIdx.y * 64 + warp * 8 + 2 * i;
        *(float4*)&out[(size_t)m * SEQ + n0] =
            make_float4(c0v.x * ATTN_SCALE, c1v.x * ATTN_SCALE, c2v.x * ATTN_SCALE, c3v.x * ATTN_SCALE);
        *(float4*)&out[(size_t)(m + 1) * SEQ + n0] =
            make_float4(c0v.y * ATTN_SCALE, c1v.y * ATTN_SCALE, c2v.y * ATTN_SCALE, c3v.y * ATTN_SCALE);
    }
}

// ---------------- fused softmax + head-mix, IN PLACE over g_attn ------------
// One block per (b, n) row. Each thread holds the float4 at column t*4 for all
// 12 heads in registers: softmax each head's row, then
// attn[i] <- attn[i] + relu(sum_k M[i,k] attn[k]) pointwise. All reads happen
// before any write to the same location (thread-private columns), so in-place
// is race-free. Saves one full 100MB r/w pass vs separate kernels.
__global__ __launch_bounds__(256) void softmax_mix_kernel()
{
    __shared__ float Ms[NH * NH];
    __shared__ float red[8];
    __shared__ float bc;
    const int t = threadIdx.x;
    const int b = blockIdx.x >> 10;
    const int n = blockIdx.x & (SEQ - 1);
    if (t < NH * NH) Ms[t] = g_M[t];

    float4 a[NH];
    #pragma unroll
    for (int h = 0; h < NH; h++) {
        float4* p = (float4*)(g_attn + ((size_t)(b * NH + h) * SEQ + n) * SEQ);
        float4 v = p[t];
        float m = fmaxf(fmaxf(v.x, v.y), fmaxf(v.z, v.w));
        #pragma unroll
        for (int o = 16; o; o >>= 1) m = fmaxf(m, __shfl_xor_sync(0xffffffffu, m, o));
        if ((t & 31) == 0) red[t >> 5] = m;
        __syncthreads();
        if (t == 0) {
            float x = red[0];
            #pragma unroll
            for (int i = 1; i < 8; i++) x = fmaxf(x, red[i]);
            bc = x;
        }
        __syncthreads();
        m = bc;
        v.x = __expf(v.x - m); v.y = __expf(v.y - m);
        v.z = __expf(v.z - m); v.w = __expf(v.w - m);
        float s = v.x + v.y + v.z + v.w;
        #pragma unroll
        for (int o = 16; o; o >>= 1) s += __shfl_xor_sync(0xffffffffu, s, o);
        __syncthreads();                 // all threads done reading bc (max)
        if ((t & 31) == 0) red[t >> 5] = s;
        __syncthreads();
        if (t == 0) {
            float x = 0.f;
            #pragma unroll
            for (int i = 0; i < 8; i++) x += red[i];
            bc = x;
        }
        __syncthreads();
        const float inv = 1.0f / bc;
        a[h] = make_float4(v.x * inv, v.y * inv, v.z * inv, v.w * inv);
        __syncthreads();                 // all threads done reading bc (sum)
    }

    #pragma unroll
    for (int i = 0; i < NH; i++) {
        float ax = 0.f, ay = 0.f, az = 0.f, aw = 0.f;
        #pragma unroll
        for (int k = 0; k < NH; k++) {
            float mm = Ms[i * NH + k];
            ax = fmaf(mm, a[k].x, ax); ay = fmaf(mm, a[k].y, ay);
            az = fmaf(mm, a[k].z, az); aw = fmaf(mm, a[k].w, aw);
        }
        float4 r;
        r.x = a[i].x + fmaxf(ax, 0.f); r.y = a[i].y + fmaxf(ay, 0.f);
        r.z = a[i].z + fmaxf(az, 0.f); r.w = a[i].w + fmaxf(aw, 0.f);
        float4* p = (float4*)(g_attn + ((size_t)(b * NH + i) * SEQ + n) * SEQ);
        p[t] = r;
    }
}

// ---------------- out_h = P2 @ V per (b,h): C[128n x 64d], K = 1024 ----------
__global__ __launch_bounds__(256) void av_kernel()
{
    __shared__ __align__(16) float Ast[32][130];   // [m][n] transposed P2 tile
    __shared__ __align__(16) float Bs2[32][64];    // [m][d]
    const int t = threadIdx.x, lane = t & 31, warp = t >> 5;
    const int bh = blockIdx.y;
    const int n0 = blockIdx.x * 128;
    const float* Ap = g_attn + (size_t)bh * NN + (size_t)n0 * SEQ;
    const float* Bp = g_v + (size_t)bh * SEQ * DH;
    const int nb = warp * 16 + (lane >> 4) * 8;
    const int db = (lane & 15) * 4;
    ull acc[4][4];
    #pragma unroll
    for (int i = 0; i < 4; i++)
        #pragma unroll
        for (int j = 0; j < 4; j++) acc[i][j] = 0ull;

    const int arow = t >> 1;              // 0..127
    const int acolq = (t & 1) * 16;       // 0 or 16
    const int vi0 = t, vi1 = t + 256;

    for (int k0 = 0; k0 < SEQ; k0 += 32) {
        float4 a0 = *(const float4*)(Ap + (size_t)arow * SEQ + k0 + acolq + 0);
        float4 a1 = *(const float4*)(Ap + (size_t)arow * SEQ + k0 + acolq + 4);
        float4 a2 = *(const float4*)(Ap + (size_t)arow * SEQ + k0 + acolq + 8);
        float4 a3 = *(const float4*)(Ap + (size_t)arow * SEQ + k0 + acolq + 12);
        float4 v0 = *(const float4*)(Bp + (size_t)(k0 + (vi0 >> 4)) * DH + (vi0 & 15) * 4);
        float4 v1 = *(const float4*)(Bp + (size_t)(k0 + (vi1 >> 4)) * DH + (vi1 & 15) * 4);
        __syncthreads();
        Ast[acolq + 0][arow] = a0.x;  Ast[acolq + 1][arow] = a0.y;
        Ast[acolq + 2][arow] = a0.z;  Ast[acolq + 3][arow] = a0.w;
        Ast[acolq + 4][arow] = a1.x;  Ast[acolq + 5][arow] = a1.y;
        Ast[acolq + 6][arow] = a1.z;  Ast[acolq + 7][arow] = a1.w;
        Ast[acolq + 8][arow] = a2.x;  Ast[acolq + 9][arow] = a2.y;
        Ast[acolq + 10][arow] = a2.z; Ast[acolq + 11][arow] = a2.w;
        Ast[acolq + 12][arow] = a3.x; Ast[acolq + 13][arow] = a3.y;
        Ast[acolq + 14][arow] = a3.z; Ast[acolq + 15][arow] = a3.w;
        *(float4*)&Bs2[vi0 >> 4][(vi0 & 15) * 4] = v0;
        *(float4*)&Bs2[vi1 >> 4][(vi1 & 15) * 4] = v1;
        __syncthreads();
        #pragma unroll
        for (int kk = 0; kk < 32; kk++) {
            ull a0u = *(const ull*)&Ast[kk][nb + 0];
            ull a1u = *(const ull*)&Ast[kk][nb + 2];
            ull a2u = *(const ull*)&Ast[kk][nb + 4];
            ull a3u = *(const ull*)&Ast[kk][nb + 6];
            ull b0 = pk2(Bs2[kk][db + 0]);
            ull b1 = pk2(Bs2[kk][db + 1]);
            ull b2 = pk2(Bs2[kk][db + 2]);
            ull b3 = pk2(Bs2[kk][db + 3]);
            fma2(acc[0][0], a0u, b0); fma2(acc[0][1], a0u, b1);
            fma2(acc[0][2], a0u, b2); fma2(acc[0][3], a0u, b3);
            fma2(acc[1][0], a1u, b0); fma2(acc[1][1], a1u, b1);
            fma2(acc[1][2], a1u, b2); fma2(acc[1][3], a1u, b3);
            fma2(acc[2][0], a2u, b0); fma2(acc[2][1], a2u, b1);
            fma2(acc[2][2], a2u, b2); fma2(acc[2][3], a2u, b3);
            fma2(acc[3][0], a3u, b0); fma2(acc[3][1], a3u, b1);
            fma2(acc[3][2], a3u, b2); fma2(acc[3][3], a3u, b3);
        }
    }

    const int bt = bh / NH, h = bh % NH;
    #pragma unroll
    for (int i = 0; i < 4; i++) {
        float2 c0v = up2(acc[i][0]), c1v = up2(acc[i][1]);
        float2 c2v = up2(acc[i][2]), c3v = up2(acc[i][3]);
        int n = n0 + nb + 2 * i;
        float* o0 = g_av + (size_t)(bt * SEQ + n) * DMODEL + h * DH + db;
        float* o1 = g_av + (size_t)(bt * SEQ + n + 1) * DMODEL + h * DH + db;
        *(float4*)o0 = make_float4(c0v.x, c1v.x, c2v.x, c3v.x);
        *(float4*)o1 = make_float4(c0v.y, c1v.y, c2v.y, c3v.y);
    }
}

// ---------------- out = g_av @ w_out^T + b_out ----------------
__global__ __launch_bounds__(256) void proj_kernel(
    const float* __restrict__ w, const float* __restrict__ bias, float* __restrict__ out)
{
    ull acc[4][4];
    #pragma unroll
    for (int i = 0; i < 4; i++)
        #pragma unroll
        for (int j = 0; j < 4; j++) acc[i][j] = 0ull;

    const float* A = g_av + (size_t)blockIdx.y * 64 * DMODEL;
    const float* B = w    + (size_t)blockIdx.x * 128 * DMODEL;
    gemm_nt<DMODEL>(A, DMODEL, B, DMODEL, acc);

    const int warp = threadIdx.x >> 5, lane = threadIdx.x & 31;
    const int c0 = blockIdx.x * 128 + lane * 4;
    const float4 bb = *(const float4*)&bias[c0];
    #pragma unroll
    for (int i = 0; i < 4; i++) {
        float2 c0v = up2(acc[i][0]), c1v = up2(acc[i][1]);
        float2 c2v = up2(acc[i][2]), c3v = up2(acc[i][3]);
        int m = blockIdx.y * 64 + warp * 8 + 2 * i;
        *(float4*)&out[(size_t)m * DMODEL + c0] =
            make_float4(c0v.x + bb.x, c1v.x + bb.y, c2v.x + bb.z, c3v.x + bb.w);
        *(float4*)&out[(size_t)(m + 1) * DMODEL + c0] =
            make_float4(c0v.y + bb.x, c1v.y + bb.y, c2v.y + bb.z, c3v.y + bb.w);
    }
}

// ---------------- launch ----------------
extern "C" void kernel_launch(void* const* d_in, const int* in_sizes, int n_in,
                              void* d_out, int out_size)
{
    const float* x     = (const float*)d_in[0];
    const float* ln_g  = (const float*)d_in[1];
    const float* ln_b  = (const float*)d_in[2];
    const float* w_qkv = (const float*)d_in[3];
    const float* w_out = (const float*)d_in[4];
    const float* b_out = (const float*)d_in[5];
    const float* theta = (const float*)d_in[6];
    const float* gnn_w = (const float*)d_in[7];
    float* out = (float*)d_out;

    ln_kernel<<<NTOK, 256>>>(x, ln_g, ln_b);
    m_kernel<<<1, 160>>>(theta, gnn_w);
    qkv_kernel<<<dim3(18, 32), 256>>>(w_qkv);                 // 2304/128 x 2048/64
    qk_kernel<<<dim3(8, 16, NBATCH * NH), 256>>>();           // 1024/128 x 1024/64 x 24
    softmax_mix_kernel<<<NBATCH * SEQ, 256>>>();              // fused, in place
    av_kernel<<<dim3(8, NBATCH * NH), 256>>>();               // 1024/128 x 24
    proj_kernel<<<dim3(6, 32), 256>>>(w_out, b_out, out);     // 768/128 x 2048/64
}